// round 8
// baseline (speedup 1.0000x reference)
#include <cuda_runtime.h>
#include <cuda_bf16.h>
#include <cstdint>

#define B_   4
#define S_   2048
#define E_   1024
#define H_   16
#define D_   64
#define QD_  1024
#define KD_  768
#define VD_  768
#define M_   (B_ * S_)          // 8192
#define BH_  (B_ * H_)          // 64

// ---------------- device scratch (no allocations allowed) ----------------
__device__ __align__(16) __nv_bfloat16 g_Ahi[M_ * E_];
__device__ __align__(16) __nv_bfloat16 g_Alo[M_ * E_];
__device__ __align__(16) __nv_bfloat16 g_Whi[E_ * E_];
__device__ __align__(16) __nv_bfloat16 g_Wlo[E_ * E_];
__device__ __align__(16) __nv_bfloat16 g_qhi[BH_ * S_ * D_];
__device__ __align__(16) __nv_bfloat16 g_qlo[BH_ * S_ * D_];
__device__ __align__(16) __nv_bfloat16 g_khi[BH_ * S_ * D_];
__device__ __align__(16) __nv_bfloat16 g_klo[BH_ * S_ * D_];
__device__ __align__(16) __nv_bfloat16 g_vhi[BH_ * S_ * D_];
__device__ __align__(16) __nv_bfloat16 g_vlo[BH_ * S_ * D_];
__device__ __align__(16) __nv_bfloat16 g_vthi[BH_ * D_ * S_];
__device__ __align__(16) __nv_bfloat16 g_vtlo[BH_ * D_ * S_];
__device__ float g_pmax[BH_ * 16 * S_];
__device__ float g_psum[BH_ * 16 * S_];
__device__ float g_rmax[BH_ * S_];
__device__ float g_rinv[BH_ * S_];

// ======================= helpers ============================
__device__ __forceinline__ uint32_t smem_u32(const void* p) {
    uint32_t a;
    asm("{ .reg .u64 t; cvta.to.shared.u64 t, %1; cvt.u32.u64 %0, t; }"
        : "=r"(a) : "l"(p));
    return a;
}
__device__ __forceinline__ void cp16(uint32_t dst, const void* src) {
    asm volatile("cp.async.cg.shared.global [%0], [%1], 16;" :: "r"(dst), "l"(src));
}
#define LDSM4(R, addr) \
    asm volatile("ldmatrix.sync.aligned.m8n8.x4.shared.b16 {%0,%1,%2,%3}, [%4];" \
                 : "=r"((R)[0]), "=r"((R)[1]), "=r"((R)[2]), "=r"((R)[3]) : "r"(addr))
#define MMA16816(c, a, b0, b1) \
    asm volatile("mma.sync.aligned.m16n8k16.row.col.f32.bf16.bf16.f32 " \
                 "{%0,%1,%2,%3}, {%4,%5,%6,%7}, {%8,%9}, {%0,%1,%2,%3};" \
                 : "+f"((c)[0]), "+f"((c)[1]), "+f"((c)[2]), "+f"((c)[3]) \
                 : "r"((a)[0]), "r"((a)[1]), "r"((a)[2]), "r"((a)[3]), "r"(b0), "r"(b1))

__device__ __forceinline__ uint32_t pack_bf2(float a, float b) {
    __nv_bfloat162 t = __floats2bfloat162_rn(a, b);
    return *(uint32_t*)&t;
}

__device__ __forceinline__ float fast_exp(float x) {
    float t = x * 1.44269504088896341f;
    t = fmaxf(t, -125.0f);
    float r = t + 12582912.0f;
    int   n = __float_as_int(r) - 0x4B400000;
    float f = t - (r - 12582912.0f);
    float p = 1.33336498e-3f;
    p = fmaf(p, f, 9.61011466e-3f);
    p = fmaf(p, f, 5.55036595e-2f);
    p = fmaf(p, f, 2.40226510e-1f);
    p = fmaf(p, f, 6.93147182e-1f);
    p = fmaf(p, f, 1.0f);
    return __int_as_float((n + 127) << 23) * p;
}

__device__ __forceinline__ void store_hilo2(
    __nv_bfloat16* Ohi, __nv_bfloat16* Olo, size_t o, float x0, float x1)
{
    __nv_bfloat162 hh = __floats2bfloat162_rn(x0, x1);
    float l0 = x0 - __bfloat162float(hh.x);
    float l1 = x1 - __bfloat162float(hh.y);
    ((__nv_bfloat162*)Ohi)[o] = hh;
    ((__nv_bfloat162*)Olo)[o] = __floats2bfloat162_rn(l0, l1);
}

// ================= generic hi/lo split tensor-core GEMM ==================
// C[M,N] = alpha*(Ahi@Bhi^T + Ahi@Blo^T + Alo@Bhi^T) + bias
// EPI=0: fp32 C.  EPI=1: bf16 hi/lo head-major.  EPI=2: AV -- A is raw fp32
// scores, normalized in-flight (p=exp(x-m)*rinv), normalized weights written
// back to C(=Wbuf), output bf16 hi/lo row-major.  EPI=3: scores -- fp32 C +
// per-(row, colblock) max/expsum partials to gpm/gps.
template<int BN, bool AF32, int EPI>
__global__ __launch_bounds__(256) void hilo_gemm(
    const void* __restrict__ Ahi_, const void* __restrict__ Alo_,
    const __nv_bfloat16* __restrict__ Bhi_, const __nv_bfloat16* __restrict__ Blo_,
    const float* __restrict__ bias, float* __restrict__ C,
    __nv_bfloat16* __restrict__ Ohi, __nv_bfloat16* __restrict__ Olo,
    const float* __restrict__ rmax, const float* __restrict__ rinv,
    float* __restrict__ gpm, float* __restrict__ gps,
    int K, int ldA, int ldB, int ldC,
    long long strideA, long long strideB,
    long long sCo, long long sCi, int zdiv, float alpha)
{
    constexpr int NI  = BN / 16;
    constexpr int SSA = 128 * 80;
    constexpr int BOF = BN * 80;
    constexpr int SS  = 2 * SSA + 2 * BOF;
    extern __shared__ __align__(16) char smem[];
    const uint32_t sbase = smem_u32(smem);
    __shared__ float s_m[128], s_r[128];

    const int tid  = threadIdx.x;
    const int lane = tid & 31;
    const int wid  = tid >> 5;
    const int m0w  = (wid >> 1) * 32;
    const int n0w  = (wid & 1) * (BN / 2);
    const int m0   = blockIdx.y * 128;
    const int n0   = blockIdx.x * BN;
    const size_t z = blockIdx.z;

    const __nv_bfloat16* Ah = nullptr;
    const __nv_bfloat16* Al = nullptr;
    const float* Af = nullptr;
    float* AfW = nullptr;
    if (AF32) {
        Af = (const float*)Ahi_ + z * strideA + (size_t)m0 * ldA;
        if (EPI == 2) AfW = C + z * strideA + (size_t)m0 * ldA;
    } else {
        Ah = (const __nv_bfloat16*)Ahi_ + z * strideA + (size_t)m0 * ldA;
        Al = (const __nv_bfloat16*)Alo_ + z * strideA + (size_t)m0 * ldA;
    }
    const __nv_bfloat16* Bh = Bhi_ + z * strideB + (size_t)n0 * ldB;
    const __nv_bfloat16* Bl = Blo_ + z * strideB + (size_t)n0 * ldB;

    if (AF32 && EPI == 2) {
        if (tid < 128) {
            s_m[tid] = rmax[z * S_ + m0 + tid];
            s_r[tid] = rinv[z * S_ + m0 + tid];
        }
        __syncthreads();
    }

    const int T = K / 32;
    float acc[2][NI][4];
    #pragma unroll
    for (int i = 0; i < 2; i++)
        #pragma unroll
        for (int j = 0; j < NI; j++)
            #pragma unroll
            for (int q = 0; q < 4; q++) acc[i][j][q] = 0.0f;

    auto load_stage = [&](int it) {
        const int st = it & 1;
        const int k0 = it * 32;
        const uint32_t sb = sbase + st * SS;
        #pragma unroll
        for (int c = tid; c < BN * 8; c += 256) {
            int tile = (c >= BN * 4) ? 1 : 0;
            int cc   = c - tile * BN * 4;
            int r    = cc >> 2, seg = cc & 3;
            const __nv_bfloat16* src = (tile ? Bl : Bh) + (size_t)r * ldB + k0 + seg * 8;
            cp16(sb + 2 * SSA + tile * BOF + r * 80 + seg * 16, src);
        }
        if (AF32) {
            char* sp = smem + st * SS;
            #pragma unroll
            for (int c = tid; c < 1024; c += 256) {
                int r = c >> 3, seg = c & 7;
                float4 v = *(const float4*)(Af + (size_t)r * ldA + k0 + seg * 4);
                if (EPI == 2) {
                    float mm = s_m[r], rv = s_r[r];
                    v.x = fast_exp(v.x - mm) * rv;
                    v.y = fast_exp(v.y - mm) * rv;
                    v.z = fast_exp(v.z - mm) * rv;
                    v.w = fast_exp(v.w - mm) * rv;
                    *(float4*)(AfW + (size_t)r * ldA + k0 + seg * 4) = v;
                }
                uint32_t h01 = pack_bf2(v.x, v.y);
                uint32_t h23 = pack_bf2(v.z, v.w);
                __nv_bfloat162 H01 = *(__nv_bfloat162*)&h01;
                __nv_bfloat162 H23 = *(__nv_bfloat162*)&h23;
                uint32_t l01 = pack_bf2(v.x - __bfloat162float(H01.x),
                                        v.y - __bfloat162float(H01.y));
                uint32_t l23 = pack_bf2(v.z - __bfloat162float(H23.x),
                                        v.w - __bfloat162float(H23.y));
                *(uint32_t*)(sp + r * 80 + seg * 8)           = h01;
                *(uint32_t*)(sp + r * 80 + seg * 8 + 4)       = h23;
                *(uint32_t*)(sp + SSA + r * 80 + seg * 8)     = l01;
                *(uint32_t*)(sp + SSA + r * 80 + seg * 8 + 4) = l23;
            }
        } else {
            #pragma unroll
            for (int c = tid; c < 1024; c += 256) {
                int tile = c >> 9;
                int r = (c >> 2) & 127, seg = c & 3;
                const __nv_bfloat16* src = (tile ? Al : Ah) + (size_t)r * ldA + k0 + seg * 8;
                cp16(sb + tile * SSA + r * 80 + seg * 16, src);
            }
        }
    };

    load_stage(0);
    asm volatile("cp.async.commit_group;" ::: "memory");

    for (int it = 0; it < T; it++) {
        if (it + 1 < T) {
            load_stage(it + 1);
            asm volatile("cp.async.commit_group;" ::: "memory");
            asm volatile("cp.async.wait_group 1;" ::: "memory");
        } else {
            asm volatile("cp.async.wait_group 0;" ::: "memory");
        }
        __syncthreads();

        const uint32_t sA = sbase + (it & 1) * SS;
        const uint32_t sB = sA + 2 * SSA;
        #pragma unroll
        for (int kk = 0; kk < 2; kk++) {
            uint32_t ah[2][4], al[2][4];
            #pragma unroll
            for (int mi = 0; mi < 2; mi++) {
                uint32_t addr = sA + ((m0w + mi * 16 + (lane & 15)) * 40
                                      + kk * 16 + ((lane >> 4) << 3)) * 2;
                LDSM4(ah[mi], addr);
                LDSM4(al[mi], addr + SSA);
            }
            uint32_t bh[NI][2], bl[NI][2];
            #pragma unroll
            for (int nj = 0; nj < NI / 2; nj++) {
                uint32_t row = n0w + nj * 16 + (lane & 7) + ((lane >> 4) << 3);
                uint32_t col = kk * 16 + (((lane >> 3) & 1) << 3);
                uint32_t addr = sB + (row * 40 + col) * 2;
                uint32_t t4[4];
                LDSM4(t4, addr);
                bh[2 * nj][0] = t4[0]; bh[2 * nj][1] = t4[1];
                bh[2 * nj + 1][0] = t4[2]; bh[2 * nj + 1][1] = t4[3];
                LDSM4(t4, addr + BOF);
                bl[2 * nj][0] = t4[0]; bl[2 * nj][1] = t4[1];
                bl[2 * nj + 1][0] = t4[2]; bl[2 * nj + 1][1] = t4[3];
            }
            #pragma unroll
            for (int mi = 0; mi < 2; mi++)
                #pragma unroll
                for (int ni = 0; ni < NI; ni++) {
                    MMA16816(acc[mi][ni], ah[mi], bh[ni][0], bh[ni][1]);
                    MMA16816(acc[mi][ni], ah[mi], bl[ni][0], bl[ni][1]);
                    MMA16816(acc[mi][ni], al[mi], bh[ni][0], bh[ni][1]);
                }
        }
        __syncthreads();
    }

    // ---------------- epilogue ----------------
    if (EPI == 0) {
        float* Cz = C + (z / zdiv) * sCo + (z % zdiv) * sCi;
        #pragma unroll
        for (int mi = 0; mi < 2; mi++)
            #pragma unroll
            for (int ni = 0; ni < NI; ni++) {
                int row = m0 + m0w + mi * 16 + (lane >> 2);
                int col = n0 + n0w + ni * 8 + ((lane & 3) << 1);
                float b0 = bias ? __ldg(bias + col) : 0.0f;
                float b1 = bias ? __ldg(bias + col + 1) : 0.0f;
                Cz[(size_t)row * ldC + col]           = acc[mi][ni][0] * alpha + b0;
                Cz[(size_t)row * ldC + col + 1]       = acc[mi][ni][1] * alpha + b1;
                Cz[(size_t)(row + 8) * ldC + col]     = acc[mi][ni][2] * alpha + b0;
                Cz[(size_t)(row + 8) * ldC + col + 1] = acc[mi][ni][3] * alpha + b1;
            }
    } else if (EPI == 1) {
        #pragma unroll
        for (int mi = 0; mi < 2; mi++)
            #pragma unroll
            for (int ni = 0; ni < NI; ni++) {
                int row = m0 + m0w + mi * 16 + (lane >> 2);
                int col = n0 + n0w + ni * 8 + ((lane & 3) << 1);
                float b0 = bias ? __ldg(bias + col) : 0.0f;
                float b1 = bias ? __ldg(bias + col + 1) : 0.0f;
                int h = col >> 6, d = col & 63;
                #pragma unroll
                for (int rr = 0; rr < 2; rr++) {
                    int r = row + rr * 8;
                    int b = r >> 11, s = r & 2047;
                    size_t o = ((((size_t)(b * 16 + h)) * S_ + s) * D_ + d) >> 1;
                    store_hilo2(Ohi, Olo, o,
                                acc[mi][ni][rr * 2 + 0] + b0,
                                acc[mi][ni][rr * 2 + 1] + b1);
                }
            }
    } else if (EPI == 2) {
        const int b = (int)z / zdiv, h = (int)z % zdiv;
        #pragma unroll
        for (int mi = 0; mi < 2; mi++)
            #pragma unroll
            for (int ni = 0; ni < NI; ni++) {
                int srow = m0 + m0w + mi * 16 + (lane >> 2);
                int col  = n0 + n0w + ni * 8 + ((lane & 3) << 1);
                #pragma unroll
                for (int rr = 0; rr < 2; rr++) {
                    int s = srow + rr * 8;
                    size_t token = (size_t)b * S_ + s;
                    size_t o = (token * E_ + h * D_ + col) >> 1;
                    store_hilo2(Ohi, Olo, o,
                                acc[mi][ni][rr * 2 + 0],
                                acc[mi][ni][rr * 2 + 1]);
                }
            }
    } else {
        // EPI == 3: scores — write raw C (alpha applied) + row stats partials
        __shared__ float pm_s[128][2];
        __shared__ float ps_s[128][2];
        __shared__ float bm_s[128];
        float* Cz = C + z * sCo;
        float vmax[2][2] = {{-1e30f, -1e30f}, {-1e30f, -1e30f}};
        #pragma unroll
        for (int mi = 0; mi < 2; mi++)
            #pragma unroll
            for (int ni = 0; ni < NI; ni++) {
                int row = m0 + m0w + mi * 16 + (lane >> 2);
                int col = n0 + n0w + ni * 8 + ((lane & 3) << 1);
                float v0 = acc[mi][ni][0] * alpha, v1 = acc[mi][ni][1] * alpha;
                float v2 = acc[mi][ni][2] * alpha, v3 = acc[mi][ni][3] * alpha;
                acc[mi][ni][0] = v0; acc[mi][ni][1] = v1;
                acc[mi][ni][2] = v2; acc[mi][ni][3] = v3;
                Cz[(size_t)row * ldC + col]           = v0;
                Cz[(size_t)row * ldC + col + 1]       = v1;
                Cz[(size_t)(row + 8) * ldC + col]     = v2;
                Cz[(size_t)(row + 8) * ldC + col + 1] = v3;
                vmax[mi][0] = fmaxf(vmax[mi][0], fmaxf(v0, v1));
                vmax[mi][1] = fmaxf(vmax[mi][1], fmaxf(v2, v3));
            }
        #pragma unroll
        for (int mi = 0; mi < 2; mi++)
            #pragma unroll
            for (int rr = 0; rr < 2; rr++) {
                float v = vmax[mi][rr];
                v = fmaxf(v, __shfl_xor_sync(0xFFFFFFFFu, v, 1));
                v = fmaxf(v, __shfl_xor_sync(0xFFFFFFFFu, v, 2));
                vmax[mi][rr] = v;
            }
        if ((lane & 3) == 0) {
            #pragma unroll
            for (int mi = 0; mi < 2; mi++)
                #pragma unroll
                for (int rr = 0; rr < 2; rr++)
                    pm_s[m0w + mi * 16 + (lane >> 2) + rr * 8][wid & 1] = vmax[mi][rr];
        }
        __syncthreads();
        if (tid < 128) bm_s[tid] = fmaxf(pm_s[tid][0], pm_s[tid][1]);
        __syncthreads();
        float esum[2][2] = {{0.0f, 0.0f}, {0.0f, 0.0f}};
        #pragma unroll
        for (int mi = 0; mi < 2; mi++) {
            float bm0 = bm_s[m0w + mi * 16 + (lane >> 2)];
            float bm1 = bm_s[m0w + mi * 16 + (lane >> 2) + 8];
            #pragma unroll
            for (int ni = 0; ni < NI; ni++) {
                esum[mi][0] += fast_exp(acc[mi][ni][0] - bm0)
                             + fast_exp(acc[mi][ni][1] - bm0);
                esum[mi][1] += fast_exp(acc[mi][ni][2] - bm1)
                             + fast_exp(acc[mi][ni][3] - bm1);
            }
        }
        #pragma unroll
        for (int mi = 0; mi < 2; mi++)
            #pragma unroll
            for (int rr = 0; rr < 2; rr++) {
                float v = esum[mi][rr];
                v += __shfl_xor_sync(0xFFFFFFFFu, v, 1);
                v += __shfl_xor_sync(0xFFFFFFFFu, v, 2);
                esum[mi][rr] = v;
            }
        if ((lane & 3) == 0) {
            #pragma unroll
            for (int mi = 0; mi < 2; mi++)
                #pragma unroll
                for (int rr = 0; rr < 2; rr++)
                    ps_s[m0w + mi * 16 + (lane >> 2) + rr * 8][wid & 1] = esum[mi][rr];
        }
        __syncthreads();
        if (tid < 128) {
            size_t o = ((size_t)z * gridDim.x + blockIdx.x) * (size_t)S_ + m0 + tid;
            gpm[o] = bm_s[tid];
            gps[o] = ps_s[tid][0] + ps_s[tid][1];
        }
    }
}

// ---------------- combine per-colblock stats into row max & 1/sum --------
__global__ __launch_bounds__(256) void combine_kernel(
    const float* __restrict__ gpm, const float* __restrict__ gps,
    float* __restrict__ rmax, float* __restrict__ rinv)
{
    int g = blockIdx.x * 256 + threadIdx.x;        // [bh*2048)
    int bh = g >> 11, r = g & 2047;
    const float* pm = gpm + (size_t)bh * 16 * S_ + r;
    const float* ps = gps + (size_t)bh * 16 * S_ + r;
    float m = -1e30f;
    #pragma unroll
    for (int jb = 0; jb < 16; jb++) m = fmaxf(m, pm[(size_t)jb * S_]);
    float s = 0.0f;
    #pragma unroll
    for (int jb = 0; jb < 16; jb++)
        s += ps[(size_t)jb * S_] * fast_exp(pm[(size_t)jb * S_] - m);
    rmax[g] = m;
    rinv[g] = 1.0f / s;
}

// ================= conversions ===========================================
__global__ __launch_bounds__(256) void conv_hilo4_kernel(
    const float4* __restrict__ in, __nv_bfloat162* __restrict__ hi,
    __nv_bfloat162* __restrict__ lo, int n4)
{
    int i = blockIdx.x * 256 + threadIdx.x;
    if (i < n4) {
        float4 v = in[i];
        __nv_bfloat162 h01 = __floats2bfloat162_rn(v.x, v.y);
        __nv_bfloat162 h23 = __floats2bfloat162_rn(v.z, v.w);
        hi[2 * i]     = h01;
        hi[2 * i + 1] = h23;
        lo[2 * i]     = __floats2bfloat162_rn(v.x - __bfloat162float(h01.x),
                                              v.y - __bfloat162float(h01.y));
        lo[2 * i + 1] = __floats2bfloat162_rn(v.z - __bfloat162float(h23.x),
                                              v.w - __bfloat162float(h23.y));
    }
}

__global__ __launch_bounds__(256) void transconv_kernel(
    const float* __restrict__ W, __nv_bfloat16* __restrict__ hi,
    __nv_bfloat16* __restrict__ lo, int K, int N)
{
    __shared__ float t[32][33];
    const int k0 = blockIdx.y * 32, n0 = blockIdx.x * 32;
    const int tx = threadIdx.x & 31, ty = threadIdx.x >> 5;
    #pragma unroll
    for (int i = 0; i < 32; i += 8)
        t[ty + i][tx] = W[(size_t)(k0 + ty + i) * N + n0 + tx];
    __syncthreads();
    #pragma unroll
    for (int i = 0; i < 32; i += 8) {
        float x = t[tx][ty + i];
        __nv_bfloat16 h = __float2bfloat16(x);
        size_t o = (size_t)(n0 + ty + i) * K + k0 + tx;
        hi[o] = h;
        lo[o] = __float2bfloat16(x - __bfloat162float(h));
    }
}

__global__ __launch_bounds__(256) void transpose_hl_kernel(
    const __nv_bfloat16* __restrict__ hi_in, const __nv_bfloat16* __restrict__ lo_in,
    __nv_bfloat16* __restrict__ hi_out, __nv_bfloat16* __restrict__ lo_out)
{
    __shared__ __nv_bfloat16 th[32][33];
    __shared__ __nv_bfloat16 tl[32][33];
    const int bh = blockIdx.z;
    const int s0 = blockIdx.x * 32, d0 = blockIdx.y * 32;
    const int tx = threadIdx.x & 31, ty = threadIdx.x >> 5;
    #pragma unroll
    for (int i = 0; i < 32; i += 8) {
        size_t src = ((size_t)bh * S_ + s0 + ty + i) * D_ + d0 + tx;
        th[ty + i][tx] = hi_in[src];
        tl[ty + i][tx] = lo_in[src];
    }
    __syncthreads();
    #pragma unroll
    for (int i = 0; i < 32; i += 8) {
        size_t dst = ((size_t)bh * D_ + d0 + ty + i) * S_ + s0 + tx;
        hi_out[dst] = th[tx][ty + i];
        lo_out[dst] = tl[tx][ty + i];
    }
}

// ---------------- launch ----------------
extern "C" void kernel_launch(void* const* d_in, const int* in_sizes, int n_in,
                              void* d_out, int out_size)
{
    const float* query = (const float*)d_in[0];
    const float* key   = (const float*)d_in[1];
    const float* value = (const float*)d_in[2];
    const float* Wq    = (const float*)d_in[3];
    const float* bq    = (const float*)d_in[4];
    const float* Wk    = (const float*)d_in[5];
    const float* bk    = (const float*)d_in[6];
    const float* Wv    = (const float*)d_in[7];
    const float* bv    = (const float*)d_in[8];
    const float* Wo    = (const float*)d_in[9];
    const float* bo    = (const float*)d_in[10];

    float* out  = (float*)d_out;                 // [B,S,E]
    float* Wbuf = out + (size_t)M_ * E_;         // [B,H,S,S]

    __nv_bfloat16 *ahi, *alo, *whi, *wlo, *qhi, *qlo, *khi, *klo;
    __nv_bfloat16 *vhi, *vlo, *vthi, *vtlo;
    float *gpm, *gps, *grm, *gri;
    cudaGetSymbolAddress((void**)&ahi,  g_Ahi);
    cudaGetSymbolAddress((void**)&alo,  g_Alo);
    cudaGetSymbolAddress((void**)&whi,  g_Whi);
    cudaGetSymbolAddress((void**)&wlo,  g_Wlo);
    cudaGetSymbolAddress((void**)&qhi,  g_qhi);
    cudaGetSymbolAddress((void**)&qlo,  g_qlo);
    cudaGetSymbolAddress((void**)&khi,  g_khi);
    cudaGetSymbolAddress((void**)&klo,  g_klo);
    cudaGetSymbolAddress((void**)&vhi,  g_vhi);
    cudaGetSymbolAddress((void**)&vlo,  g_vlo);
    cudaGetSymbolAddress((void**)&vthi, g_vthi);
    cudaGetSymbolAddress((void**)&vtlo, g_vtlo);
    cudaGetSymbolAddress((void**)&gpm,  g_pmax);
    cudaGetSymbolAddress((void**)&gps,  g_psum);
    cudaGetSymbolAddress((void**)&grm,  g_rmax);
    cudaGetSymbolAddress((void**)&gri,  g_rinv);

    const int SMEM_P = 2 * (2 * 128 * 80 + 2 * 128 * 80);  // BN=128: 81920
    const int SMEM_A = 2 * (2 * 128 * 80 + 2 * 64 * 80);   // BN=64:  61440
    cudaFuncSetAttribute(hilo_gemm<128, false, 0>,
                         cudaFuncAttributeMaxDynamicSharedMemorySize, SMEM_P);
    cudaFuncSetAttribute(hilo_gemm<128, false, 1>,
                         cudaFuncAttributeMaxDynamicSharedMemorySize, SMEM_P);
    cudaFuncSetAttribute(hilo_gemm<128, false, 3>,
                         cudaFuncAttributeMaxDynamicSharedMemorySize, SMEM_P);
    cudaFuncSetAttribute(hilo_gemm<64, true, 2>,
                         cudaFuncAttributeMaxDynamicSharedMemorySize, SMEM_A);

    // ---- projections (write head-major bf16 hi/lo directly) ----
    conv_hilo4_kernel<<<(M_ * QD_ / 4 + 255) / 256, 256>>>(
        (const float4*)query, (__nv_bfloat162*)ahi, (__nv_bfloat162*)alo, M_ * QD_ / 4);
    transconv_kernel<<<dim3(E_ / 32, QD_ / 32), 256>>>(Wq, whi, wlo, QD_, E_);
    hilo_gemm<128, false, 1><<<dim3(E_ / 128, M_ / 128, 1), 256, SMEM_P>>>(
        ahi, alo, whi, wlo, bq, nullptr, qhi, qlo, nullptr, nullptr, nullptr, nullptr,
        QD_, QD_, QD_, E_, 0, 0, 0, 0, 1, 1.0f);

    conv_hilo4_kernel<<<(M_ * KD_ / 4 + 255) / 256, 256>>>(
        (const float4*)key, (__nv_bfloat162*)ahi, (__nv_bfloat162*)alo, M_ * KD_ / 4);
    transconv_kernel<<<dim3(E_ / 32, KD_ / 32), 256>>>(Wk, whi, wlo, KD_, E_);
    hilo_gemm<128, false, 1><<<dim3(E_ / 128, M_ / 128, 1), 256, SMEM_P>>>(
        ahi, alo, whi, wlo, bk, nullptr, khi, klo, nullptr, nullptr, nullptr, nullptr,
        KD_, KD_, KD_, E_, 0, 0, 0, 0, 1, 1.0f);

    conv_hilo4_kernel<<<(M_ * VD_ / 4 + 255) / 256, 256>>>(
        (const float4*)value, (__nv_bfloat162*)ahi, (__nv_bfloat162*)alo, M_ * VD_ / 4);
    transconv_kernel<<<dim3(E_ / 32, VD_ / 32), 256>>>(Wv, whi, wlo, VD_, E_);
    hilo_gemm<128, false, 1><<<dim3(E_ / 128, M_ / 128, 1), 256, SMEM_P>>>(
        ahi, alo, whi, wlo, bv, nullptr, vhi, vlo, nullptr, nullptr, nullptr, nullptr,
        VD_, VD_, VD_, E_, 0, 0, 0, 0, 1, 1.0f);

    transpose_hl_kernel<<<dim3(S_ / 32, D_ / 32, BH_), 256>>>(vhi, vlo, vthi, vtlo);

    // ---- scores + row-stats partials ----
    hilo_gemm<128, false, 3><<<dim3(S_ / 128, S_ / 128, BH_), 256, SMEM_P>>>(
        qhi, qlo, khi, klo, nullptr, Wbuf, nullptr, nullptr,
        nullptr, nullptr, gpm, gps,
        D_, D_, D_, S_,
        (long long)S_ * D_, (long long)S_ * D_,
        (long long)S_ * S_, 0, 1, 0.125f);

    // ---- combine stats ----
    combine_kernel<<<(BH_ * S_) / 256, 256>>>(gpm, gps, grm, gri);

    // ---- AV: normalize raw scores in-flight, write weights, output ctx ----
    hilo_gemm<64, true, 2><<<dim3(1, S_ / 128, BH_), 256, SMEM_A>>>(
        Wbuf, nullptr, vthi, vtlo, nullptr, Wbuf, ahi, alo, grm, gri, nullptr, nullptr,
        S_, S_, S_, E_,
        (long long)S_ * S_, (long long)D_ * S_,
        0, 0, 16, 1.0f);

    // ---- output projection (fp32 out + bias) ----
    transconv_kernel<<<dim3(E_ / 32, E_ / 32), 256>>>(Wo, whi, wlo, E_, E_);
    hilo_gemm<128, false, 0><<<dim3(E_ / 128, M_ / 128, 1), 256, SMEM_P>>>(
        ahi, alo, whi, wlo, bo, out, nullptr, nullptr, nullptr, nullptr, nullptr, nullptr,
        E_, E_, E_, E_, 0, 0, 0, 0, 1, 1.0f);
}

// round 10
// speedup vs baseline: 1.1877x; 1.1877x over previous
#include <cuda_runtime.h>
#include <cuda_bf16.h>
#include <cuda_fp16.h>
#include <cstdint>

#define B_   4
#define S_   2048
#define E_   1024
#define H_   16
#define D_   64
#define QD_  1024
#define KD_  768
#define VD_  768
#define M_   (B_ * S_)          // 8192
#define BH_  (B_ * H_)          // 64

// ---------------- device scratch (no allocations allowed) ----------------
__device__ __align__(16) __nv_bfloat16 g_Ahi[M_ * E_];
__device__ __align__(16) __nv_bfloat16 g_Alo[M_ * E_];
__device__ __align__(16) __nv_bfloat16 g_Whi[E_ * E_];
__device__ __align__(16) __nv_bfloat16 g_Wlo[E_ * E_];
__device__ __align__(16) __half g_Wohi[E_ * E_];
__device__ __align__(16) __half g_Wolo[E_ * E_];
__device__ __align__(16) __half g_qhi[BH_ * S_ * D_];
__device__ __align__(16) __half g_qlo[BH_ * S_ * D_];
__device__ __align__(16) __half g_khi[BH_ * S_ * D_];
__device__ __align__(16) __half g_klo[BH_ * S_ * D_];
__device__ __align__(16) __half g_vhi[BH_ * S_ * D_];
__device__ __align__(16) __half g_vlo[BH_ * S_ * D_];
__device__ __align__(16) __half g_vthi[BH_ * D_ * S_];
__device__ __align__(16) __half g_vtlo[BH_ * D_ * S_];
__device__ __align__(16) __half g_ctxh[M_ * E_];

// ======================= helpers ============================
__device__ __forceinline__ uint32_t smem_u32(const void* p) {
    uint32_t a;
    asm("{ .reg .u64 t; cvta.to.shared.u64 t, %1; cvt.u32.u64 %0, t; }"
        : "=r"(a) : "l"(p));
    return a;
}
__device__ __forceinline__ void cp16(uint32_t dst, const void* src) {
    asm volatile("cp.async.cg.shared.global [%0], [%1], 16;" :: "r"(dst), "l"(src));
}
#define LDSM4(R, addr) \
    asm volatile("ldmatrix.sync.aligned.m8n8.x4.shared.b16 {%0,%1,%2,%3}, [%4];" \
                 : "=r"((R)[0]), "=r"((R)[1]), "=r"((R)[2]), "=r"((R)[3]) : "r"(addr))
#define MMA_BF16(c, a, b0, b1) \
    asm volatile("mma.sync.aligned.m16n8k16.row.col.f32.bf16.bf16.f32 " \
                 "{%0,%1,%2,%3}, {%4,%5,%6,%7}, {%8,%9}, {%0,%1,%2,%3};" \
                 : "+f"((c)[0]), "+f"((c)[1]), "+f"((c)[2]), "+f"((c)[3]) \
                 : "r"((a)[0]), "r"((a)[1]), "r"((a)[2]), "r"((a)[3]), "r"(b0), "r"(b1))
#define MMA_F16(c, a, b0, b1) \
    asm volatile("mma.sync.aligned.m16n8k16.row.col.f32.f16.f16.f32 " \
                 "{%0,%1,%2,%3}, {%4,%5,%6,%7}, {%8,%9}, {%0,%1,%2,%3};" \
                 : "+f"((c)[0]), "+f"((c)[1]), "+f"((c)[2]), "+f"((c)[3]) \
                 : "r"((a)[0]), "r"((a)[1]), "r"((a)[2]), "r"((a)[3]), "r"(b0), "r"(b1))

__device__ __forceinline__ float fast_exp(float x) {
    float t = x * 1.44269504088896341f;
    t = fmaxf(t, -125.0f);
    float r = t + 12582912.0f;
    int   n = __float_as_int(r) - 0x4B400000;
    float f = t - (r - 12582912.0f);
    float p = 1.33336498e-3f;
    p = fmaf(p, f, 9.61011466e-3f);
    p = fmaf(p, f, 5.55036595e-2f);
    p = fmaf(p, f, 2.40226510e-1f);
    p = fmaf(p, f, 6.93147182e-1f);
    p = fmaf(p, f, 1.0f);
    return __int_as_float((n + 127) << 23) * p;
}

// fp32 pair -> fp16 hi/lo pair at half2-element index o
__device__ __forceinline__ void store_hl_h2(
    void* Ohi, void* Olo, size_t o, float x0, float x1)
{
    __half2 hh = __floats2half2_rn(x0, x1);
    ((__half2*)Ohi)[o] = hh;
    float l0 = x0 - __half2float(__low2half(hh));
    float l1 = x1 - __half2float(__high2half(hh));
    ((__half2*)Olo)[o] = __floats2half2_rn(l0, l1);
}

// ================= generic split tensor-core GEMM ========================
// MODE 0: bf16 3-term  (A = bf16 hi/lo gmem)         C = Ah·Bh + Ah·Bl + Al·Bh
// MODE 1: fp16 2-term  (A = fp16 hi gmem)            C = A·Bh + A·Bl
// MODE 2: fp16 2-term  (A = fp32 gmem, cvt in load)  C = fp16(A)·Bh + fp16(A)·Bl
// B: [N,K] 16-bit hi/lo row-major.  Tiles 128 x BN, BK=32, 2-stage cp.async.
// EPI 0: fp32 C (+bias, alpha, batch strides)
// EPI 1: fp16 hi/lo head-major [bh][s][d] (+bias)
// EPI 2: fp16 hi row-major [token][E] at col (z%zdiv)*64 + col
template<int BN, int MODE, int EPI>
__global__ __launch_bounds__(256) void hilo_gemm(
    const void* __restrict__ Ahi_, const void* __restrict__ Alo_,
    const void* __restrict__ Bhi_, const void* __restrict__ Blo_,
    const float* __restrict__ bias, float* __restrict__ C,
    void* __restrict__ Ohi, void* __restrict__ Olo,
    int K, int ldA, int ldB, int ldC,
    long long strideA, long long strideB,
    long long sCo, long long sCi, int zdiv, float alpha)
{
    constexpr int NI     = BN / 16;
    constexpr int SSA    = 128 * 80;
    constexpr int ATILES = (MODE == 0) ? 2 : 1;
    constexpr int BOF    = BN * 80;
    constexpr int SS     = ATILES * SSA + 2 * BOF;
    extern __shared__ __align__(16) char smem[];
    const uint32_t sbase = smem_u32(smem);

    const int tid  = threadIdx.x;
    const int lane = tid & 31;
    const int wid  = tid >> 5;
    const int m0w  = (wid >> 1) * 32;
    const int n0w  = (wid & 1) * (BN / 2);
    const int m0   = blockIdx.y * 128;
    const int n0   = blockIdx.x * BN;
    const size_t z = blockIdx.z;

    const uint16_t* Ah16 = nullptr;
    const uint16_t* Al16 = nullptr;
    const float*    Af   = nullptr;
    if (MODE == 2) {
        Af = (const float*)Ahi_ + z * strideA + (size_t)m0 * ldA;
    } else {
        Ah16 = (const uint16_t*)Ahi_ + z * strideA + (size_t)m0 * ldA;
        if (MODE == 0)
            Al16 = (const uint16_t*)Alo_ + z * strideA + (size_t)m0 * ldA;
    }
    const uint16_t* Bh = (const uint16_t*)Bhi_ + z * strideB + (size_t)n0 * ldB;
    const uint16_t* Bl = (const uint16_t*)Blo_ + z * strideB + (size_t)n0 * ldB;

    const int T = K / 32;
    float acc[2][NI][4];
    #pragma unroll
    for (int i = 0; i < 2; i++)
        #pragma unroll
        for (int j = 0; j < NI; j++)
            #pragma unroll
            for (int q = 0; q < 4; q++) acc[i][j][q] = 0.0f;

    auto load_stage = [&](int it) {
        const int st = it & 1;
        const int k0 = it * 32;
        const uint32_t sb = sbase + st * SS;
        #pragma unroll
        for (int c = tid; c < BN * 8; c += 256) {
            int tile = (c >= BN * 4) ? 1 : 0;
            int cc   = c - tile * BN * 4;
            int r    = cc >> 2, seg = cc & 3;
            const uint16_t* src = (tile ? Bl : Bh) + (size_t)r * ldB + k0 + seg * 8;
            cp16(sb + ATILES * SSA + tile * BOF + r * 80 + seg * 16, src);
        }
        if (MODE == 0) {
            #pragma unroll
            for (int c = tid; c < 1024; c += 256) {
                int tile = c >> 9;
                int r = (c >> 2) & 127, seg = c & 3;
                const uint16_t* src = (tile ? Al16 : Ah16) + (size_t)r * ldA + k0 + seg * 8;
                cp16(sb + tile * SSA + r * 80 + seg * 16, src);
            }
        } else if (MODE == 1) {
            #pragma unroll
            for (int c = tid; c < 512; c += 256) {
                int r = c >> 2, seg = c & 3;
                cp16(sb + r * 80 + seg * 16, Ah16 + (size_t)r * ldA + k0 + seg * 8);
            }
        } else {
            char* sp = smem + st * SS;
            #pragma unroll
            for (int c = tid; c < 1024; c += 256) {
                int r = c >> 3, seg = c & 7;
                float4 v = *(const float4*)(Af + (size_t)r * ldA + k0 + seg * 4);
                __half2 h01 = __floats2half2_rn(v.x, v.y);
                __half2 h23 = __floats2half2_rn(v.z, v.w);
                *(uint32_t*)(sp + r * 80 + seg * 8)     = *(uint32_t*)&h01;
                *(uint32_t*)(sp + r * 80 + seg * 8 + 4) = *(uint32_t*)&h23;
            }
        }
    };

    load_stage(0);
    asm volatile("cp.async.commit_group;" ::: "memory");

    for (int it = 0; it < T; it++) {
        if (it + 1 < T) {
            load_stage(it + 1);
            asm volatile("cp.async.commit_group;" ::: "memory");
            asm volatile("cp.async.wait_group 1;" ::: "memory");
        } else {
            asm volatile("cp.async.wait_group 0;" ::: "memory");
        }
        __syncthreads();

        const uint32_t sA = sbase + (it & 1) * SS;
        const uint32_t sB = sA + ATILES * SSA;
        #pragma unroll
        for (int kk = 0; kk < 2; kk++) {
            uint32_t ah[2][4], al[2][4];
            #pragma unroll
            for (int mi = 0; mi < 2; mi++) {
                uint32_t addr = sA + ((m0w + mi * 16 + (lane & 15)) * 40
                                      + kk * 16 + ((lane >> 4) << 3)) * 2;
                LDSM4(ah[mi], addr);
                if (MODE == 0) LDSM4(al[mi], addr + SSA);
            }
            uint32_t bh[NI][2], bl[NI][2];
            #pragma unroll
            for (int nj = 0; nj < NI / 2; nj++) {
                uint32_t row = n0w + nj * 16 + (lane & 7) + ((lane >> 4) << 3);
                uint32_t col = kk * 16 + (((lane >> 3) & 1) << 3);
                uint32_t addr = sB + (row * 40 + col) * 2;
                uint32_t t4[4];
                LDSM4(t4, addr);
                bh[2 * nj][0] = t4[0]; bh[2 * nj][1] = t4[1];
                bh[2 * nj + 1][0] = t4[2]; bh[2 * nj + 1][1] = t4[3];
                LDSM4(t4, addr + BOF);
                bl[2 * nj][0] = t4[0]; bl[2 * nj][1] = t4[1];
                bl[2 * nj + 1][0] = t4[2]; bl[2 * nj + 1][1] = t4[3];
            }
            #pragma unroll
            for (int mi = 0; mi < 2; mi++)
                #pragma unroll
                for (int ni = 0; ni < NI; ni++) {
                    if (MODE == 0) {
                        MMA_BF16(acc[mi][ni], ah[mi], bh[ni][0], bh[ni][1]);
                        MMA_BF16(acc[mi][ni], ah[mi], bl[ni][0], bl[ni][1]);
                        MMA_BF16(acc[mi][ni], al[mi], bh[ni][0], bh[ni][1]);
                    } else {
                        MMA_F16(acc[mi][ni], ah[mi], bh[ni][0], bh[ni][1]);
                        MMA_F16(acc[mi][ni], ah[mi], bl[ni][0], bl[ni][1]);
                    }
                }
        }
        __syncthreads();
    }

    // ---------------- epilogue ----------------
    if (EPI == 0) {
        float* Cz = C + (z / zdiv) * sCo + (z % zdiv) * sCi;
        #pragma unroll
        for (int mi = 0; mi < 2; mi++)
            #pragma unroll
            for (int ni = 0; ni < NI; ni++) {
                int row = m0 + m0w + mi * 16 + (lane >> 2);
                int col = n0 + n0w + ni * 8 + ((lane & 3) << 1);
                float b0 = bias ? __ldg(bias + col) : 0.0f;
                float b1 = bias ? __ldg(bias + col + 1) : 0.0f;
                Cz[(size_t)row * ldC + col]           = acc[mi][ni][0] * alpha + b0;
                Cz[(size_t)row * ldC + col + 1]       = acc[mi][ni][1] * alpha + b1;
                Cz[(size_t)(row + 8) * ldC + col]     = acc[mi][ni][2] * alpha + b0;
                Cz[(size_t)(row + 8) * ldC + col + 1] = acc[mi][ni][3] * alpha + b1;
            }
    } else if (EPI == 1) {
        #pragma unroll
        for (int mi = 0; mi < 2; mi++)
            #pragma unroll
            for (int ni = 0; ni < NI; ni++) {
                int row = m0 + m0w + mi * 16 + (lane >> 2);
                int col = n0 + n0w + ni * 8 + ((lane & 3) << 1);
                float b0 = bias ? __ldg(bias + col) : 0.0f;
                float b1 = bias ? __ldg(bias + col + 1) : 0.0f;
                int h = col >> 6, d = col & 63;
                #pragma unroll
                for (int rr = 0; rr < 2; rr++) {
                    int r = row + rr * 8;
                    int b = r >> 11, s = r & 2047;
                    size_t o = ((((size_t)(b * 16 + h)) * S_ + s) * D_ + d) >> 1;
                    store_hl_h2(Ohi, Olo, o,
                                acc[mi][ni][rr * 2 + 0] + b0,
                                acc[mi][ni][rr * 2 + 1] + b1);
                }
            }
    } else {
        const int b = (int)z / zdiv, h = (int)z % zdiv;
        #pragma unroll
        for (int mi = 0; mi < 2; mi++)
            #pragma unroll
            for (int ni = 0; ni < NI; ni++) {
                int srow = m0 + m0w + mi * 16 + (lane >> 2);
                int col  = n0 + n0w + ni * 8 + ((lane & 3) << 1);
                #pragma unroll
                for (int rr = 0; rr < 2; rr++) {
                    int s = srow + rr * 8;
                    size_t token = (size_t)b * S_ + s;
                    size_t o = (token * E_ + h * D_ + col) >> 1;
                    ((__half2*)Ohi)[o] =
                        __floats2half2_rn(acc[mi][ni][rr * 2 + 0],
                                          acc[mi][ni][rr * 2 + 1]);
                }
            }
    }
}

// ================= conversions ===========================================
__global__ __launch_bounds__(256) void conv_hilo4_kernel(
    const float4* __restrict__ in, __nv_bfloat162* __restrict__ hi,
    __nv_bfloat162* __restrict__ lo, int n4)
{
    int i = blockIdx.x * 256 + threadIdx.x;
    if (i < n4) {
        float4 v = in[i];
        __nv_bfloat162 h01 = __floats2bfloat162_rn(v.x, v.y);
        __nv_bfloat162 h23 = __floats2bfloat162_rn(v.z, v.w);
        hi[2 * i]     = h01;
        hi[2 * i + 1] = h23;
        lo[2 * i]     = __floats2bfloat162_rn(v.x - __bfloat162float(h01.x),
                                              v.y - __bfloat162float(h01.y));
        lo[2 * i + 1] = __floats2bfloat162_rn(v.z - __bfloat162float(h23.x),
                                              v.w - __bfloat162float(h23.y));
    }
}

// W[K,N] fp32 -> Wt[N,K] bf16 hi/lo
__global__ __launch_bounds__(256) void transconv_bf_kernel(
    const float* __restrict__ W, __nv_bfloat16* __restrict__ hi,
    __nv_bfloat16* __restrict__ lo, int K, int N)
{
    __shared__ float t[32][33];
    const int k0 = blockIdx.y * 32, n0 = blockIdx.x * 32;
    const int tx = threadIdx.x & 31, ty = threadIdx.x >> 5;
    #pragma unroll
    for (int i = 0; i < 32; i += 8)
        t[ty + i][tx] = W[(size_t)(k0 + ty + i) * N + n0 + tx];
    __syncthreads();
    #pragma unroll
    for (int i = 0; i < 32; i += 8) {
        float x = t[tx][ty + i];
        __nv_bfloat16 h = __float2bfloat16(x);
        size_t o = (size_t)(n0 + ty + i) * K + k0 + tx;
        hi[o] = h;
        lo[o] = __float2bfloat16(x - __bfloat162float(h));
    }
}

// W[K,N] fp32 -> Wt[N,K] fp16 hi/lo
__global__ __launch_bounds__(256) void transconv_h_kernel(
    const float* __restrict__ W, __half* __restrict__ hi,
    __half* __restrict__ lo, int K, int N)
{
    __shared__ float t[32][33];
    const int k0 = blockIdx.y * 32, n0 = blockIdx.x * 32;
    const int tx = threadIdx.x & 31, ty = threadIdx.x >> 5;
    #pragma unroll
    for (int i = 0; i < 32; i += 8)
        t[ty + i][tx] = W[(size_t)(k0 + ty + i) * N + n0 + tx];
    __syncthreads();
    #pragma unroll
    for (int i = 0; i < 32; i += 8) {
        float x = t[tx][ty + i];
        __half h = __float2half_rn(x);
        size_t o = (size_t)(n0 + ty + i) * K + k0 + tx;
        hi[o] = h;
        lo[o] = __float2half_rn(x - __half2float(h));
    }
}

// [bh][s][d] 16-bit -> [bh][d][s] 16-bit (hi and lo together)
__global__ __launch_bounds__(256) void transpose16_kernel(
    const uint16_t* __restrict__ hi_in, const uint16_t* __restrict__ lo_in,
    uint16_t* __restrict__ hi_out, uint16_t* __restrict__ lo_out)
{
    __shared__ uint16_t th[32][33];
    __shared__ uint16_t tl[32][33];
    const int bh = blockIdx.z;
    const int s0 = blockIdx.x * 32, d0 = blockIdx.y * 32;
    const int tx = threadIdx.x & 31, ty = threadIdx.x >> 5;
    #pragma unroll
    for (int i = 0; i < 32; i += 8) {
        size_t src = ((size_t)bh * S_ + s0 + ty + i) * D_ + d0 + tx;
        th[ty + i][tx] = hi_in[src];
        tl[ty + i][tx] = lo_in[src];
    }
    __syncthreads();
    #pragma unroll
    for (int i = 0; i < 32; i += 8) {
        size_t dst = ((size_t)bh * D_ + d0 + ty + i) * S_ + s0 + tx;
        hi_out[dst] = th[tx][ty + i];
        lo_out[dst] = tl[tx][ty + i];
    }
}

// ---------------- fused softmax row pass (in-place, float4) --------------
__global__ __launch_bounds__(256) void softmax_kernel(float* __restrict__ Wbuf)
{
    const size_t row = blockIdx.x;
    float4* p = (float4*)(Wbuf + row * S_);
    const int t = threadIdx.x;
    __shared__ float red[8];
    __shared__ float s_m, s_r;

    float4 va = p[t];
    float4 vb = p[t + 256];
    float m = fmaxf(fmaxf(fmaxf(va.x, va.y), fmaxf(va.z, va.w)),
                    fmaxf(fmaxf(vb.x, vb.y), fmaxf(vb.z, vb.w)));
    #pragma unroll
    for (int o = 16; o; o >>= 1) m = fmaxf(m, __shfl_xor_sync(0xFFFFFFFFu, m, o));
    if ((t & 31) == 0) red[t >> 5] = m;
    __syncthreads();
    if (t == 0) {
        float mm = red[0];
        #pragma unroll
        for (int i = 1; i < 8; i++) mm = fmaxf(mm, red[i]);
        s_m = mm;
    }
    __syncthreads();
    m = s_m;

    va.x = fast_exp(va.x - m); va.y = fast_exp(va.y - m);
    va.z = fast_exp(va.z - m); va.w = fast_exp(va.w - m);
    vb.x = fast_exp(vb.x - m); vb.y = fast_exp(vb.y - m);
    vb.z = fast_exp(vb.z - m); vb.w = fast_exp(vb.w - m);
    float s = va.x + va.y + va.z + va.w + vb.x + vb.y + vb.z + vb.w;
    #pragma unroll
    for (int o = 16; o; o >>= 1) s += __shfl_xor_sync(0xFFFFFFFFu, s, o);
    if ((t & 31) == 0) red[t >> 5] = s;
    __syncthreads();
    if (t == 0) {
        float tot = 0.0f;
        #pragma unroll
        for (int i = 0; i < 8; i++) tot += red[i];
        s_r = 1.0f / tot;
    }
    __syncthreads();
    const float r = s_r;
    va.x *= r; va.y *= r; va.z *= r; va.w *= r;
    vb.x *= r; vb.y *= r; vb.z *= r; vb.w *= r;
    p[t] = va;
    p[t + 256] = vb;
}

// ---------------- launch ----------------
extern "C" void kernel_launch(void* const* d_in, const int* in_sizes, int n_in,
                              void* d_out, int out_size)
{
    const float* query = (const float*)d_in[0];
    const float* key   = (const float*)d_in[1];
    const float* value = (const float*)d_in[2];
    const float* Wq    = (const float*)d_in[3];
    const float* bq    = (const float*)d_in[4];
    const float* Wk    = (const float*)d_in[5];
    const float* bk    = (const float*)d_in[6];
    const float* Wv    = (const float*)d_in[7];
    const float* bv    = (const float*)d_in[8];
    const float* Wo    = (const float*)d_in[9];
    const float* bo    = (const float*)d_in[10];

    float* out  = (float*)d_out;                 // [B,S,E]
    float* Wbuf = out + (size_t)M_ * E_;         // [B,H,S,S]

    __nv_bfloat16 *ahi, *alo, *whi, *wlo;
    __half *wohi, *wolo, *qhi, *qlo, *khi, *klo, *vhi, *vlo, *vthi, *vtlo, *ctxh;
    cudaGetSymbolAddress((void**)&ahi,  g_Ahi);
    cudaGetSymbolAddress((void**)&alo,  g_Alo);
    cudaGetSymbolAddress((void**)&whi,  g_Whi);
    cudaGetSymbolAddress((void**)&wlo,  g_Wlo);
    cudaGetSymbolAddress((void**)&wohi, g_Wohi);
    cudaGetSymbolAddress((void**)&wolo, g_Wolo);
    cudaGetSymbolAddress((void**)&qhi,  g_qhi);
    cudaGetSymbolAddress((void**)&qlo,  g_qlo);
    cudaGetSymbolAddress((void**)&khi,  g_khi);
    cudaGetSymbolAddress((void**)&klo,  g_klo);
    cudaGetSymbolAddress((void**)&vhi,  g_vhi);
    cudaGetSymbolAddress((void**)&vlo,  g_vlo);
    cudaGetSymbolAddress((void**)&vthi, g_vthi);
    cudaGetSymbolAddress((void**)&vtlo, g_vtlo);
    cudaGetSymbolAddress((void**)&ctxh, g_ctxh);

    const int SMEM_PROJ = 2 * (2 * 128 * 80 + 2 * 128 * 80);  // 81920
    const int SMEM_H16  = 2 * (1 * 128 * 80 + 2 * 128 * 80);  // 61440
    const int SMEM_AV   = 2 * (1 * 128 * 80 + 2 * 64 * 80);   // 40960
    cudaFuncSetAttribute(hilo_gemm<128, 0, 1>,
                         cudaFuncAttributeMaxDynamicSharedMemorySize, SMEM_PROJ);
    cudaFuncSetAttribute(hilo_gemm<128, 1, 0>,
                         cudaFuncAttributeMaxDynamicSharedMemorySize, SMEM_H16);
    cudaFuncSetAttribute(hilo_gemm<64, 2, 2>,
                         cudaFuncAttributeMaxDynamicSharedMemorySize, SMEM_AV);

    // ---- projections (bf16 3-term, write head-major fp16 hi/lo) ----
    conv_hilo4_kernel<<<(M_ * QD_ / 4 + 255) / 256, 256>>>(
        (const float4*)query, (__nv_bfloat162*)ahi, (__nv_bfloat162*)alo, M_ * QD_ / 4);
    transconv_bf_kernel<<<dim3(E_ / 32, QD_ / 32), 256>>>(Wq, whi, wlo, QD_, E_);
    hilo_gemm<128, 0, 1><<<dim3(E_ / 128, M_ / 128, 1), 256, SMEM_PROJ>>>(
        ahi, alo, whi, wlo, bq, nullptr, qhi, qlo,
        QD_, QD_, QD_, E_, 0, 0, 0, 0, 1, 1.0f);

    conv_hilo4_kernel<<<(M_ * KD_ / 4 + 255) / 256, 256>>>(
        (const float4*)key, (__nv_bfloat162*)ahi, (__nv_bfloat162*)alo, M_ * KD_ / 4);
    transconv_bf_kernel<<<dim3(E_ / 32, KD_ / 32), 256>>>(Wk, whi, wlo, KD_, E_);
    hilo_gemm<128, 0, 1><<<dim3(E_ / 128, M_ / 128, 1), 256, SMEM_PROJ>>>(
        ahi, alo, whi, wlo, bk, nullptr, khi, klo,
        KD_, KD_, KD_, E_, 0, 0, 0, 0, 1, 1.0f);

    conv_hilo4_kernel<<<(M_ * VD_ / 4 + 255) / 256, 256>>>(
        (const float4*)value, (__nv_bfloat162*)ahi, (__nv_bfloat162*)alo, M_ * VD_ / 4);
    transconv_bf_kernel<<<dim3(E_ / 32, VD_ / 32), 256>>>(Wv, whi, wlo, VD_, E_);
    hilo_gemm<128, 0, 1><<<dim3(E_ / 128, M_ / 128, 1), 256, SMEM_PROJ>>>(
        ahi, alo, whi, wlo, bv, nullptr, vhi, vlo,
        VD_, VD_, VD_, E_, 0, 0, 0, 0, 1, 1.0f);

    transpose16_kernel<<<dim3(S_ / 32, D_ / 32, BH_), 256>>>(
        (const uint16_t*)vhi, (const uint16_t*)vlo,
        (uint16_t*)vthi, (uint16_t*)vtlo);

    // ---- scores: fp16 2-term, Wbuf = 0.125 * q.k ----
    hilo_gemm<128, 1, 0><<<dim3(S_ / 128, S_ / 128, BH_), 256, SMEM_H16>>>(
        qhi, nullptr, khi, klo, nullptr, Wbuf, nullptr, nullptr,
        D_, D_, D_, S_,
        (long long)S_ * D_, (long long)S_ * D_,
        (long long)S_ * S_, 0, 1, 0.125f);

    // ---- softmax in-place ----
    softmax_kernel<<<(size_t)BH_ * S_, 256>>>(Wbuf);

    // ---- AV: fp16 2-term, A = normalized P fp32 -> fp16, out ctx fp16 ----
    hilo_gemm<64, 2, 2><<<dim3(1, S_ / 128, BH_), 256, SMEM_AV>>>(
        Wbuf, nullptr, vthi, vtlo, nullptr, nullptr, ctxh, nullptr,
        S_, S_, S_, E_,
        (long long)S_ * S_, (long long)D_ * S_,
        0, 0, 16, 1.0f);

    // ---- output projection: fp16 2-term (A = ctx fp16) ----
    transconv_h_kernel<<<dim3(E_ / 32, E_ / 32), 256>>>(Wo, wohi, wolo, E_, E_);
    hilo_gemm<128, 1, 0><<<dim3(E_ / 128, M_ / 128, 1), 256, SMEM_H16>>>(
        ctxh, nullptr, wohi, wolo, bo, out, nullptr, nullptr,
        E_, E_, E_, E_, 0, 0, 0, 0, 1, 1.0f);
}